// round 5
// baseline (speedup 1.0000x reference)
#include <cuda_runtime.h>

__device__ __forceinline__ float dot4(float4 x, float4 y) {
    return fmaf(x.x, y.x, fmaf(x.y, y.y, fmaf(x.z, y.z, x.w * y.w)));
}

// ---------------------------------------------------------------------------
// Single fused kernel, 512 threads/block, 2 batch elements per thread.
//
// Setup (per block, warps 0-7; one (direction, quantity) per warp):
//   dir = warp>>2, q = warp&3, lane = e
//     q0: uq_e = WiQ[e,:]@w_q,  cq_e = WiQ[e,:]@b_q
//     q1: uk_e = WiK[e,:]@w_k
//     q2: uv_e = WiV[e,:]@w_k,  cv_e = WiV[e,:]@b_k
//     q3: g_e  = sum_d Wf[d] * Wo[d,e]
//   -> smem; then warps 0/1 combine into the 8 scalar constants:
//     alpha=(uq.uk)/sqrt32, gamma=((cq+bq).uk)/sqrt32,
//     K1=0.5*g.uv, R=g.(cv+bv)+Wf.bo
// All other warps issue their batch-data loads before the barrier, so the
// setup latency overlaps the data fetch.
// ---------------------------------------------------------------------------
__global__ void __launch_bounds__(512, 4)
fused_kernel(const float* __restrict__ gA, const float* __restrict__ gB,
             const float* __restrict__ WA, const float* __restrict__ bA,
             const float* __restrict__ WB, const float* __restrict__ bB,
             const float* __restrict__ Wi_AB, const float* __restrict__ bi_AB,
             const float* __restrict__ Wo_AB, const float* __restrict__ bo_AB,
             const float* __restrict__ Wi_BA, const float* __restrict__ bi_BA,
             const float* __restrict__ Wo_BA, const float* __restrict__ bo_BA,
             const float* __restrict__ Wf, const float* __restrict__ bf,
             float* __restrict__ out, int nT, int B)
{
    __shared__ float sm[2][6][32];   // per dir: uq,cq,uk,uv,cv,g
    __shared__ float sC[9];

    const int t = blockIdx.x * 512 + threadIdx.x;
    const bool act = t < nT;

    // ---- batch-data loads in flight before any setup/barrier ----
    float2 A0, A1, A2; float4 Bv;
    if (act) {
        const float2* gA2 = (const float2*)gA;
        A0 = gA2[3 * t]; A1 = gA2[3 * t + 1]; A2 = gA2[3 * t + 2];
        Bv = ((const float4*)gB)[t];
    }

    const int warp = threadIdx.x >> 5;
    const int e    = threadIdx.x & 31;

    // ---- phase A: 8 warps compute the derived vectors ----
    if (warp < 8) {
        const int dir = warp >> 2;        // 0 = AB, 1 = BA
        const int q   = warp & 3;
        const float* Wi  = dir ? Wi_BA : Wi_AB;
        const float* Wo  = dir ? Wo_BA : Wo_AB;
        const float* q_w = dir ? WB : WA;  const float* q_b = dir ? bB : bA;
        const float* k_w = dir ? WA : WB;  const float* k_b = dir ? bA : bB;

        if (q == 0) {
            const float4* R4 = (const float4*)(Wi + e * 32);
            const float4* V1 = (const float4*)q_w;
            const float4* V2 = (const float4*)q_b;
            float s1 = 0.f, s2 = 0.f;
            #pragma unroll
            for (int i = 0; i < 8; ++i) {
                const float4 r = R4[i];
                s1 += dot4(r, V1[i]);
                s2 += dot4(r, V2[i]);
            }
            sm[dir][0][e] = s1;   // uq
            sm[dir][1][e] = s2;   // cq (bias added later)
        } else if (q == 1) {
            const float4* R4 = (const float4*)(Wi + (32 + e) * 32);
            const float4* V1 = (const float4*)k_w;
            float s1 = 0.f;
            #pragma unroll
            for (int i = 0; i < 8; ++i) s1 += dot4(R4[i], V1[i]);
            sm[dir][2][e] = s1;   // uk
        } else if (q == 2) {
            const float4* R4 = (const float4*)(Wi + (64 + e) * 32);
            const float4* V1 = (const float4*)k_w;
            const float4* V2 = (const float4*)k_b;
            float s1 = 0.f, s2 = 0.f;
            #pragma unroll
            for (int i = 0; i < 8; ++i) {
                const float4 r = R4[i];
                s1 += dot4(r, V1[i]);
                s2 += dot4(r, V2[i]);
            }
            sm[dir][3][e] = s1;   // uv
            sm[dir][4][e] = s2;   // cv (bias added later)
        } else {
            float s1 = 0.f;
            #pragma unroll
            for (int d = 0; d < 32; ++d)
                s1 = fmaf(Wf[d], Wo[d * 32 + e], s1);
            sm[dir][5][e] = s1;   // g
        }
    }
    __syncthreads();

    // ---- phase B: warps 0/1 combine into scalar constants ----
    if (warp < 2) {
        const int dir = warp;
        const float* bi = dir ? bi_BA : bi_AB;
        const float* bo = dir ? bo_BA : bo_AB;
        const float uq = sm[dir][0][e];
        const float cq = sm[dir][1][e] + bi[e];
        const float uk = sm[dir][2][e];
        const float uv = sm[dir][3][e];
        const float cv = sm[dir][4][e] + bi[64 + e];
        const float g  = sm[dir][5][e];

        float alpha = uq * uk;
        float gamma = cq * uk;
        float kk    = g * uv;
        float rr    = fmaf(Wf[e], bo[e], g * cv);
        #pragma unroll
        for (int off = 16; off; off >>= 1) {
            alpha += __shfl_xor_sync(0xffffffffu, alpha, off);
            gamma += __shfl_xor_sync(0xffffffffu, gamma, off);
            kk    += __shfl_xor_sync(0xffffffffu, kk, off);
            rr    += __shfl_xor_sync(0xffffffffu, rr, off);
        }
        if (e == 0) {
            const float inv_sqrtE = 0.17677669529663688f;  // 1/sqrt(32)
            sC[dir * 4 + 0] = alpha * inv_sqrtE;
            sC[dir * 4 + 1] = gamma * inv_sqrtE;
            sC[dir * 4 + 2] = 0.5f * kk;
            sC[dir * 4 + 3] = rr;
            if (dir == 0) sC[8] = bf[0];
        }
    }
    __syncthreads();

    const float C0 = sC[0], C1 = sC[1], C2 = sC[2], C3 = sC[3];
    const float C4 = sC[4], C5 = sC[5], C6 = sC[6], C7 = sC[7];
    const float K0 = fmaf(0.5f, C3 + C7, sC[8]);

    // ---- main compute: 2 elements per thread ----
    if (act) {
        const float a[6] = {A0.x, A0.y, A1.x, A1.y, A2.x, A2.y};
        const float b[4] = {Bv.x, Bv.y, Bv.z, Bv.w};
        float r[2];

        #pragma unroll
        for (int q = 0; q < 2; ++q) {
            const float a0 = a[3 * q], a1 = a[3 * q + 1], a2 = a[3 * q + 2];
            const float b0 = b[2 * q], b1 = b[2 * q + 1];

            // AB: softmax over 2 kv tokens -> sigmoid
            const float db = b1 - b0;
            float S;
            {
                const float l0 = fmaf(C0, a0, C1);
                const float l1 = fmaf(C0, a1, C1);
                const float l2 = fmaf(C0, a2, C1);
                const float s0 = __fdividef(1.f, 1.f + __expf(-l0 * db));
                const float s1 = __fdividef(1.f, 1.f + __expf(-l1 * db));
                const float s2 = __fdividef(1.f, 1.f + __expf(-l2 * db));
                S = (fmaf(db, s0, b0) + fmaf(db, s1, b0) + fmaf(db, s2, b0))
                    * (1.f / 3.f);
            }

            // BA: softmax over 3 kv tokens, for each of 2 queries
            float T = 0.f;
            #pragma unroll
            for (int j = 0; j < 2; ++j) {
                const float bj = (j == 0) ? b0 : b1;
                const float wj = fmaf(C4, bj, C5);
                const float z0 = wj * a0, z1 = wj * a1, z2 = wj * a2;
                const float m  = fmaxf(z0, fmaxf(z1, z2));
                const float e0 = __expf(z0 - m);
                const float e1 = __expf(z1 - m);
                const float e2 = __expf(z2 - m);
                T += __fdividef(fmaf(a0, e0, fmaf(a1, e1, a2 * e2)),
                                e0 + e1 + e2);
            }
            T *= 0.5f;

            const float y = fmaf(C2, S, fmaf(C6, T, K0));
            r[q] = (y >= 0.f) ? y : 0.01f * y;
        }
        ((float2*)out)[t] = make_float2(r[0], r[1]);
    }

    // odd-B tail (dead for B = 524288)
    if ((B & 1) && t == 0) {
        const int idx = B - 1;
        const float a0 = gA[3 * idx], a1 = gA[3 * idx + 1], a2 = gA[3 * idx + 2];
        const float b0 = gB[2 * idx], b1 = gB[2 * idx + 1];
        const float db = b1 - b0;
        float S;
        {
            const float l0 = fmaf(C0, a0, C1);
            const float l1 = fmaf(C0, a1, C1);
            const float l2 = fmaf(C0, a2, C1);
            S  = fmaf(db, __fdividef(1.f, 1.f + __expf(-l0 * db)), b0);
            S += fmaf(db, __fdividef(1.f, 1.f + __expf(-l1 * db)), b0);
            S += fmaf(db, __fdividef(1.f, 1.f + __expf(-l2 * db)), b0);
            S *= (1.f / 3.f);
        }
        float T = 0.f;
        for (int j = 0; j < 2; ++j) {
            const float bj = (j == 0) ? b0 : b1;
            const float wj = fmaf(C4, bj, C5);
            const float z0 = wj * a0, z1 = wj * a1, z2 = wj * a2;
            const float m  = fmaxf(z0, fmaxf(z1, z2));
            const float e0 = __expf(z0 - m), e1 = __expf(z1 - m), e2 = __expf(z2 - m);
            T += __fdividef(fmaf(a0, e0, fmaf(a1, e1, a2 * e2)), e0 + e1 + e2);
        }
        T *= 0.5f;
        const float y = fmaf(C2, S, fmaf(C6, T, K0));
        out[idx] = (y >= 0.f) ? y : 0.01f * y;
    }
}

extern "C" void kernel_launch(void* const* d_in, const int* in_sizes, int n_in,
                              void* d_out, int out_size)
{
    const float* gA    = (const float*)d_in[0];   // [B,3]
    const float* gB    = (const float*)d_in[1];   // [B,2]
    const float* WA    = (const float*)d_in[2];   // [32,1]
    const float* bA    = (const float*)d_in[3];   // [32]
    const float* WB    = (const float*)d_in[4];
    const float* bB    = (const float*)d_in[5];
    const float* Wi_AB = (const float*)d_in[6];   // [96,32]
    const float* bi_AB = (const float*)d_in[7];   // [96]
    const float* Wo_AB = (const float*)d_in[8];   // [32,32]
    const float* bo_AB = (const float*)d_in[9];   // [32]
    const float* Wi_BA = (const float*)d_in[10];
    const float* bi_BA = (const float*)d_in[11];
    const float* Wo_BA = (const float*)d_in[12];
    const float* bo_BA = (const float*)d_in[13];
    const float* Wf    = (const float*)d_in[14];  // [1,32]
    const float* bf    = (const float*)d_in[15];  // [1]

    const int B  = in_sizes[0] / 3;
    const int nT = B / 2;
    int grid = (nT + 511) / 512;
    if (grid < 1) grid = 1;

    fused_kernel<<<grid, 512>>>(gA, gB, WA, bA, WB, bB,
                                Wi_AB, bi_AB, Wo_AB, bo_AB,
                                Wi_BA, bi_BA, Wo_BA, bo_BA,
                                Wf, bf, (float*)d_out, nT, B);
}

// round 6
// speedup vs baseline: 1.2448x; 1.2448x over previous
#include <cuda_runtime.h>

// ---------------------------------------------------------------------------
// One fused kernel. 512 threads/block, 2 batch elements per thread.
//
// Phase A (all threads): coalesced copy of weights into smem.
//   smWi[dir]: 96x32 padded to stride 33 (row reads conflict-free).
//   smWo[dir]: 32x32 natural (column-broadcast reads conflict-free).
//   sV: small vectors (WA,bA,WB,bB,Wf,bo*,bi*).
// Phase B (warps 0-1, one per direction): matvecs from smem + shfl reduce
//   -> 8 scalar constants in sC.
// Main phase: closed-form evaluation, 2 elements/thread.
// ---------------------------------------------------------------------------

#define P 33                      // padded row stride for Wi in smem
// sV offsets
#define V_QWA 0
#define V_BA  32
#define V_QWB 64
#define V_BB  96
#define V_WF  128
#define V_BOAB 160
#define V_BOBA 192
#define V_BIAB 224
#define V_BIBA 320

__global__ void __launch_bounds__(512, 3)
fused_kernel(const float* __restrict__ gA, const float* __restrict__ gB,
             const float* __restrict__ WA, const float* __restrict__ bA,
             const float* __restrict__ WB, const float* __restrict__ bB,
             const float* __restrict__ Wi_AB, const float* __restrict__ bi_AB,
             const float* __restrict__ Wo_AB, const float* __restrict__ bo_AB,
             const float* __restrict__ Wi_BA, const float* __restrict__ bi_BA,
             const float* __restrict__ Wo_BA, const float* __restrict__ bo_BA,
             const float* __restrict__ Wf, const float* __restrict__ bf,
             float* __restrict__ out, int nT, int B)
{
    __shared__ float smWi[2][96 * P];   // 25.3 KB
    __shared__ float smWo[2][32 * 32];  // 8 KB
    __shared__ float sV[416];
    __shared__ float sC[9];

    const int tid = threadIdx.x;
    const int t   = blockIdx.x * 512 + tid;
    const bool act = t < nT;

    // ---- batch-data loads in flight first ----
    float2 A0, A1, A2; float4 Bv;
    if (act) {
        const float2* gA2 = (const float2*)gA;
        A0 = gA2[3 * t]; A1 = gA2[3 * t + 1]; A2 = gA2[3 * t + 2];
        Bv = ((const float4*)gB)[t];
    }

    // ---- phase A: coalesced staging of weights into smem ----
    // Wi: 3072 floats = 768 float4 each. float4 k -> flat n=4k, row n>>5, col n&31.
    {
        const float4* src0 = (const float4*)Wi_AB;
        const float4* src1 = (const float4*)Wi_BA;
        #pragma unroll
        for (int k = tid; k < 768; k += 512) {
            const int r = k >> 3, c = (k & 7) << 2;   // 8 float4 per 32-col row
            float4 v = src0[k];
            float* d = &smWi[0][r * P + c];
            d[0] = v.x; d[1] = v.y; d[2] = v.z; d[3] = v.w;
            v = src1[k];
            d = &smWi[1][r * P + c];
            d[0] = v.x; d[1] = v.y; d[2] = v.z; d[3] = v.w;
        }
    }
    // Wo: 1024 floats = 256 float4 each; threads 0-255 -> AB, 256-511 -> BA.
    {
        const int dir = tid >> 8;
        const int k   = tid & 255;
        const float4* src = dir ? (const float4*)Wo_BA : (const float4*)Wo_AB;
        ((float4*)smWo[dir])[k] = src[k];
    }
    // Small vectors (each thread at most one scalar load).
    if (tid < 32)              sV[V_QWA + tid]        = WA[tid];
    else if (tid < 64)         sV[V_BA  + tid - 32]   = bA[tid - 32];
    else if (tid < 96)         sV[V_QWB + tid - 64]   = WB[tid - 64];
    else if (tid < 128)        sV[V_BB  + tid - 96]   = bB[tid - 96];
    else if (tid < 160)        sV[V_WF  + tid - 128]  = Wf[tid - 128];
    else if (tid < 192)        sV[V_BOAB + tid - 160] = bo_AB[tid - 160];
    else if (tid < 224)        sV[V_BOBA + tid - 192] = bo_BA[tid - 192];
    else if (tid < 320)        sV[V_BIAB + tid - 224] = bi_AB[tid - 224];
    else if (tid < 416)        sV[V_BIBA + tid - 320] = bi_BA[tid - 320];
    else if (tid == 416)       sC[8] = bf[0];
    __syncthreads();

    // ---- phase B: 2 warps compute the 8 derived constants from smem ----
    const int warp = tid >> 5;
    const int e    = tid & 31;
    if (warp < 2) {
        const int dir = warp;                 // 0 = AB, 1 = BA
        const int qw = dir ? V_QWB : V_QWA;
        const int qb = dir ? V_BB  : V_BA;
        const int kw = dir ? V_QWA : V_QWB;
        const int kb = dir ? V_BA  : V_BB;
        const int bi = dir ? V_BIBA : V_BIAB;
        const int bo = dir ? V_BOBA : V_BOAB;

        const float* rq = &smWi[dir][e * P];          // Wq row e
        const float* rk = &smWi[dir][(32 + e) * P];   // Wk row e
        const float* rv = &smWi[dir][(64 + e) * P];   // Wv row e
        const float* wo = smWo[dir];

        float uq = 0.f, cq = 0.f, uk = 0.f, uv = 0.f, cv = 0.f, g = 0.f;
        #pragma unroll
        for (int d = 0; d < 32; ++d) {
            const float wq = rq[d], wkv = rk[d], wvv = rv[d];
            uq = fmaf(wq,  sV[qw + d], uq);
            cq = fmaf(wq,  sV[qb + d], cq);
            uk = fmaf(wkv, sV[kw + d], uk);
            uv = fmaf(wvv, sV[kw + d], uv);
            cv = fmaf(wvv, sV[kb + d], cv);
            g  = fmaf(sV[V_WF + d], wo[d * 32 + e], g);
        }
        cq += sV[bi + e];
        cv += sV[bi + 64 + e];

        float alpha = uq * uk;
        float gamma = cq * uk;
        float kk    = g * uv;
        float rr    = fmaf(sV[V_WF + e], sV[bo + e], g * cv);
        #pragma unroll
        for (int off = 16; off; off >>= 1) {
            alpha += __shfl_xor_sync(0xffffffffu, alpha, off);
            gamma += __shfl_xor_sync(0xffffffffu, gamma, off);
            kk    += __shfl_xor_sync(0xffffffffu, kk, off);
            rr    += __shfl_xor_sync(0xffffffffu, rr, off);
        }
        if (e == 0) {
            const float inv_sqrtE = 0.17677669529663688f;  // 1/sqrt(32)
            sC[dir * 4 + 0] = alpha * inv_sqrtE;
            sC[dir * 4 + 1] = gamma * inv_sqrtE;
            sC[dir * 4 + 2] = 0.5f * kk;
            sC[dir * 4 + 3] = rr;
        }
    }
    __syncthreads();

    const float C0 = sC[0], C1 = sC[1], C2 = sC[2], C3 = sC[3];
    const float C4 = sC[4], C5 = sC[5], C6 = sC[6], C7 = sC[7];
    const float K0 = fmaf(0.5f, C3 + C7, sC[8]);

    // ---- main compute: 2 elements per thread ----
    if (act) {
        const float a[6] = {A0.x, A0.y, A1.x, A1.y, A2.x, A2.y};
        const float b[4] = {Bv.x, Bv.y, Bv.z, Bv.w};
        float r[2];

        #pragma unroll
        for (int q = 0; q < 2; ++q) {
            const float a0 = a[3 * q], a1 = a[3 * q + 1], a2 = a[3 * q + 2];
            const float b0 = b[2 * q], b1 = b[2 * q + 1];

            // AB: softmax over 2 kv tokens -> sigmoid
            const float db = b1 - b0;
            float S;
            {
                const float l0 = fmaf(C0, a0, C1);
                const float l1 = fmaf(C0, a1, C1);
                const float l2 = fmaf(C0, a2, C1);
                const float s0 = __fdividef(1.f, 1.f + __expf(-l0 * db));
                const float s1 = __fdividef(1.f, 1.f + __expf(-l1 * db));
                const float s2 = __fdividef(1.f, 1.f + __expf(-l2 * db));
                S = (fmaf(db, s0, b0) + fmaf(db, s1, b0) + fmaf(db, s2, b0))
                    * (1.f / 3.f);
            }

            // BA: softmax over 3 kv tokens, for each of 2 queries
            float T = 0.f;
            #pragma unroll
            for (int j = 0; j < 2; ++j) {
                const float bj = (j == 0) ? b0 : b1;
                const float wj = fmaf(C4, bj, C5);
                const float z0 = wj * a0, z1 = wj * a1, z2 = wj * a2;
                const float m  = fmaxf(z0, fmaxf(z1, z2));
                const float e0 = __expf(z0 - m);
                const float e1 = __expf(z1 - m);
                const float e2 = __expf(z2 - m);
                T += __fdividef(fmaf(a0, e0, fmaf(a1, e1, a2 * e2)),
                                e0 + e1 + e2);
            }
            T *= 0.5f;

            const float y = fmaf(C2, S, fmaf(C6, T, K0));
            r[q] = (y >= 0.f) ? y : 0.01f * y;
        }
        ((float2*)out)[t] = make_float2(r[0], r[1]);
    }

    // odd-B tail (dead for B = 524288)
    if ((B & 1) && t == 0) {
        const int idx = B - 1;
        const float a0 = gA[3 * idx], a1 = gA[3 * idx + 1], a2 = gA[3 * idx + 2];
        const float b0 = gB[2 * idx], b1 = gB[2 * idx + 1];
        const float db = b1 - b0;
        float S;
        {
            const float l0 = fmaf(C0, a0, C1);
            const float l1 = fmaf(C0, a1, C1);
            const float l2 = fmaf(C0, a2, C1);
            S  = fmaf(db, __fdividef(1.f, 1.f + __expf(-l0 * db)), b0);
            S += fmaf(db, __fdividef(1.f, 1.f + __expf(-l1 * db)), b0);
            S += fmaf(db, __fdividef(1.f, 1.f + __expf(-l2 * db)), b0);
            S *= (1.f / 3.f);
        }
        float T = 0.f;
        for (int j = 0; j < 2; ++j) {
            const float bj = (j == 0) ? b0 : b1;
            const float wj = fmaf(C4, bj, C5);
            const float z0 = wj * a0, z1 = wj * a1, z2 = wj * a2;
            const float m  = fmaxf(z0, fmaxf(z1, z2));
            const float e0 = __expf(z0 - m), e1 = __expf(z1 - m), e2 = __expf(z2 - m);
            T += __fdividef(fmaf(a0, e0, fmaf(a1, e1, a2 * e2)), e0 + e1 + e2);
        }
        T *= 0.5f;
        const float y = fmaf(C2, S, fmaf(C6, T, K0));
        out[idx] = (y >= 0.f) ? y : 0.01f * y;
    }
}

extern "C" void kernel_launch(void* const* d_in, const int* in_sizes, int n_in,
                              void* d_out, int out_size)
{
    const float* gA    = (const float*)d_in[0];   // [B,3]
    const float* gB    = (const float*)d_in[1];   // [B,2]
    const float* WA    = (const float*)d_in[2];   // [32,1]
    const float* bA    = (const float*)d_in[3];   // [32]
    const float* WB    = (const float*)d_in[4];
    const float* bB    = (const float*)d_in[5];
    const float* Wi_AB = (const float*)d_in[6];   // [96,32]
    const float* bi_AB = (const float*)d_in[7];   // [96]
    const float* Wo_AB = (const float*)d_in[8];   // [32,32]
    const float* bo_AB = (const float*)d_in[9];   // [32]
    const float* Wi_BA = (const float*)d_in[10];
    const float* bi_BA = (const float*)d_in[11];
    const float* Wo_BA = (const float*)d_in[12];
    const float* bo_BA = (const float*)d_in[13];
    const float* Wf    = (const float*)d_in[14];  // [1,32]
    const float* bf    = (const float*)d_in[15];  // [1]

    const int B  = in_sizes[0] / 3;
    const int nT = B / 2;
    int grid = (nT + 511) / 512;
    if (grid < 1) grid = 1;

    fused_kernel<<<grid, 512>>>(gA, gB, WA, bA, WB, bB,
                                Wi_AB, bi_AB, Wo_AB, bo_AB,
                                Wi_BA, bi_BA, Wo_BA, bo_BA,
                                Wf, bf, (float*)d_out, nT, B);
}

// round 7
// speedup vs baseline: 1.5387x; 1.2362x over previous
#include <cuda_runtime.h>

// ---------------------------------------------------------------------------
// One fused kernel. 512 threads/block, 4 batch elements per thread (256 blocks
// for B=524288). Per-block setup: coalesced smem staging of weights, then
// 2 warps derive the 8 scalar constants. Batch loads (5x LDG.128/thread) are
// issued before staging so DRAM latency overlaps setup.
// ---------------------------------------------------------------------------

#define P 33                      // padded row stride for Wi in smem
// sV offsets
#define V_QWA 0
#define V_BA  32
#define V_QWB 64
#define V_BB  96
#define V_WF  128
#define V_BOAB 160
#define V_BOBA 192
#define V_BIAB 224
#define V_BIBA 320

__global__ void __launch_bounds__(512, 2)
fused_kernel(const float* __restrict__ gA, const float* __restrict__ gB,
             const float* __restrict__ WA, const float* __restrict__ bA,
             const float* __restrict__ WB, const float* __restrict__ bB,
             const float* __restrict__ Wi_AB, const float* __restrict__ bi_AB,
             const float* __restrict__ Wo_AB, const float* __restrict__ bo_AB,
             const float* __restrict__ Wi_BA, const float* __restrict__ bi_BA,
             const float* __restrict__ Wo_BA, const float* __restrict__ bo_BA,
             const float* __restrict__ Wf, const float* __restrict__ bf,
             float* __restrict__ out, int nT, int B)
{
    __shared__ float smWi[2][96 * P];
    __shared__ float smWo[2][32 * 32];
    __shared__ float sV[416];
    __shared__ float sC[9];

    const int tid = threadIdx.x;
    const int t   = blockIdx.x * 512 + tid;     // group of 4 elements
    const bool act = t < nT;

    // ---- batch-data loads in flight first (5x LDG.128) ----
    float4 A0, A1, A2, B0, B1;
    if (act) {
        const float4* gA4 = (const float4*)gA;
        const float4* gB4 = (const float4*)gB;
        A0 = gA4[3 * t]; A1 = gA4[3 * t + 1]; A2 = gA4[3 * t + 2];
        B0 = gB4[2 * t]; B1 = gB4[2 * t + 1];
    }

    // ---- phase A: coalesced staging of weights into smem ----
    {
        const float4* src0 = (const float4*)Wi_AB;
        const float4* src1 = (const float4*)Wi_BA;
        #pragma unroll
        for (int k = tid; k < 768; k += 512) {
            const int r = k >> 3, c = (k & 7) << 2;
            float4 v = src0[k];
            float* d = &smWi[0][r * P + c];
            d[0] = v.x; d[1] = v.y; d[2] = v.z; d[3] = v.w;
            v = src1[k];
            d = &smWi[1][r * P + c];
            d[0] = v.x; d[1] = v.y; d[2] = v.z; d[3] = v.w;
        }
    }
    {
        const int dir = tid >> 8;
        const int k   = tid & 255;
        const float4* src = dir ? (const float4*)Wo_BA : (const float4*)Wo_AB;
        ((float4*)smWo[dir])[k] = src[k];
    }
    if (tid < 32)              sV[V_QWA + tid]        = WA[tid];
    else if (tid < 64)         sV[V_BA  + tid - 32]   = bA[tid - 32];
    else if (tid < 96)         sV[V_QWB + tid - 64]   = WB[tid - 64];
    else if (tid < 128)        sV[V_BB  + tid - 96]   = bB[tid - 96];
    else if (tid < 160)        sV[V_WF  + tid - 128]  = Wf[tid - 128];
    else if (tid < 192)        sV[V_BOAB + tid - 160] = bo_AB[tid - 160];
    else if (tid < 224)        sV[V_BOBA + tid - 192] = bo_BA[tid - 192];
    else if (tid < 320)        sV[V_BIAB + tid - 224] = bi_AB[tid - 224];
    else if (tid < 416)        sV[V_BIBA + tid - 320] = bi_BA[tid - 320];
    else if (tid == 416)       sC[8] = bf[0];
    __syncthreads();

    // ---- phase B: 2 warps derive the 8 scalar constants ----
    const int warp = tid >> 5;
    const int e    = tid & 31;
    if (warp < 2) {
        const int dir = warp;
        const int qw = dir ? V_QWB : V_QWA;
        const int qb = dir ? V_BB  : V_BA;
        const int kw = dir ? V_QWA : V_QWB;
        const int kb = dir ? V_BA  : V_BB;
        const int bi = dir ? V_BIBA : V_BIAB;
        const int bo = dir ? V_BOBA : V_BOAB;

        const float* rq = &smWi[dir][e * P];
        const float* rk = &smWi[dir][(32 + e) * P];
        const float* rv = &smWi[dir][(64 + e) * P];
        const float* wo = smWo[dir];

        float uq = 0.f, cq = 0.f, uk = 0.f, uv = 0.f, cv = 0.f, g = 0.f;
        #pragma unroll
        for (int d = 0; d < 32; ++d) {
            const float wq = rq[d], wkv = rk[d], wvv = rv[d];
            uq = fmaf(wq,  sV[qw + d], uq);
            cq = fmaf(wq,  sV[qb + d], cq);
            uk = fmaf(wkv, sV[kw + d], uk);
            uv = fmaf(wvv, sV[kw + d], uv);
            cv = fmaf(wvv, sV[kb + d], cv);
            g  = fmaf(sV[V_WF + d], wo[d * 32 + e], g);
        }
        cq += sV[bi + e];
        cv += sV[bi + 64 + e];

        float alpha = uq * uk;
        float gamma = cq * uk;
        float kk    = g * uv;
        float rr    = fmaf(sV[V_WF + e], sV[bo + e], g * cv);
        #pragma unroll
        for (int off = 16; off; off >>= 1) {
            alpha += __shfl_xor_sync(0xffffffffu, alpha, off);
            gamma += __shfl_xor_sync(0xffffffffu, gamma, off);
            kk    += __shfl_xor_sync(0xffffffffu, kk, off);
            rr    += __shfl_xor_sync(0xffffffffu, rr, off);
        }
        if (e == 0) {
            const float inv_sqrtE = 0.17677669529663688f;  // 1/sqrt(32)
            sC[dir * 4 + 0] = alpha * inv_sqrtE;
            sC[dir * 4 + 1] = gamma * inv_sqrtE;
            sC[dir * 4 + 2] = 0.5f * kk;
            sC[dir * 4 + 3] = rr;
        }
    }
    __syncthreads();

    const float C0 = sC[0], C1 = sC[1], C2 = sC[2], C3 = sC[3];
    const float C4 = sC[4], C5 = sC[5], C6 = sC[6], C7 = sC[7];
    const float K0 = fmaf(0.5f, C3 + C7, sC[8]);

    // ---- main compute: 4 elements per thread ----
    if (act) {
        const float a[12] = {A0.x, A0.y, A0.z, A0.w, A1.x, A1.y, A1.z, A1.w,
                             A2.x, A2.y, A2.z, A2.w};
        const float b[8]  = {B0.x, B0.y, B0.z, B0.w, B1.x, B1.y, B1.z, B1.w};
        float r[4];

        #pragma unroll
        for (int q = 0; q < 4; ++q) {
            const float a0 = a[3 * q], a1 = a[3 * q + 1], a2 = a[3 * q + 2];
            const float b0 = b[2 * q], b1 = b[2 * q + 1];

            // AB: mean of 3 sigmoids
            const float db = b1 - b0;
            const float l0 = fmaf(C0, a0, C1) * db;
            const float l1 = fmaf(C0, a1, C1) * db;
            const float l2 = fmaf(C0, a2, C1) * db;
            const float s0 = __fdividef(1.f, 1.f + __expf(-l0));
            const float s1 = __fdividef(1.f, 1.f + __expf(-l1));
            const float s2 = __fdividef(1.f, 1.f + __expf(-l2));
            const float S = fmaf(db, (s0 + s1 + s2) * (1.f / 3.f), b0);

            // BA: 3-way softmax per query, normalized by middle exp
            // (|z| small enough that no max-subtraction is needed)
            float T = 0.f;
            #pragma unroll
            for (int j = 0; j < 2; ++j) {
                const float bj = (j == 0) ? b0 : b1;
                const float wj = fmaf(C4, bj, C5);
                const float u = __expf(wj * (a0 - a1));
                const float w = __expf(wj * (a2 - a1));
                T += __fdividef(fmaf(a0, u, fmaf(a2, w, a1)), u + w + 1.f);
            }
            T *= 0.5f;

            const float y = fmaf(C2, S, fmaf(C6, T, K0));
            r[q] = (y >= 0.f) ? y : 0.01f * y;
        }
        ((float4*)out)[t] = make_float4(r[0], r[1], r[2], r[3]);
    }

    // tail for B % 4 != 0 (dead for B = 524288)
    if (blockIdx.x == 0 && tid == 0 && (B & 3)) {
        for (int idx = nT * 4; idx < B; ++idx) {
            const float a0 = gA[3 * idx], a1 = gA[3 * idx + 1], a2 = gA[3 * idx + 2];
            const float b0 = gB[2 * idx], b1 = gB[2 * idx + 1];
            const float db = b1 - b0;
            const float l0 = fmaf(C0, a0, C1) * db;
            const float l1 = fmaf(C0, a1, C1) * db;
            const float l2 = fmaf(C0, a2, C1) * db;
            const float s0 = __fdividef(1.f, 1.f + __expf(-l0));
            const float s1 = __fdividef(1.f, 1.f + __expf(-l1));
            const float s2 = __fdividef(1.f, 1.f + __expf(-l2));
            const float S = fmaf(db, (s0 + s1 + s2) * (1.f / 3.f), b0);
            float T = 0.f;
            for (int j = 0; j < 2; ++j) {
                const float bj = (j == 0) ? b0 : b1;
                const float wj = fmaf(C4, bj, C5);
                const float u = __expf(wj * (a0 - a1));
                const float w = __expf(wj * (a2 - a1));
                T += __fdividef(fmaf(a0, u, fmaf(a2, w, a1)), u + w + 1.f);
            }
            T *= 0.5f;
            const float y = fmaf(C2, S, fmaf(C6, T, K0));
            out[idx] = (y >= 0.f) ? y : 0.01f * y;
        }
    }
}

extern "C" void kernel_launch(void* const* d_in, const int* in_sizes, int n_in,
                              void* d_out, int out_size)
{
    const float* gA    = (const float*)d_in[0];   // [B,3]
    const float* gB    = (const float*)d_in[1];   // [B,2]
    const float* WA    = (const float*)d_in[2];   // [32,1]
    const float* bA    = (const float*)d_in[3];   // [32]
    const float* WB    = (const float*)d_in[4];
    const float* bB    = (const float*)d_in[5];
    const float* Wi_AB = (const float*)d_in[6];   // [96,32]
    const float* bi_AB = (const float*)d_in[7];   // [96]
    const float* Wo_AB = (const float*)d_in[8];   // [32,32]
    const float* bo_AB = (const float*)d_in[9];   // [32]
    const float* Wi_BA = (const float*)d_in[10];
    const float* bi_BA = (const float*)d_in[11];
    const float* Wo_BA = (const float*)d_in[12];
    const float* bo_BA = (const float*)d_in[13];
    const float* Wf    = (const float*)d_in[14];  // [1,32]
    const float* bf    = (const float*)d_in[15];  // [1]

    const int B  = in_sizes[0] / 3;
    const int nT = B / 4;                          // groups of 4 elements
    int grid = (nT + 511) / 512;
    if (grid < 1) grid = 1;

    fused_kernel<<<grid, 512>>>(gA, gB, WA, bA, WB, bB,
                                Wi_AB, bi_AB, Wo_AB, bo_AB,
                                Wi_BA, bi_BA, Wo_BA, bo_BA,
                                Wf, bf, (float*)d_out, nT, B);
}